// round 2
// baseline (speedup 1.0000x reference)
#include <cuda_runtime.h>
#include <math.h>
#include <stdint.h>

// Problem constants
#define BB 4
#define HH 128
#define WW 128
#define CC 512
#define NTOK 16384            // H*W
#define NHEAD 8
#define DHEAD 64
#define MTOT (BB*NTOK)        // 65536
#define NCHUNK 32             // colsum chunks per batch
#define GSPLIT 8              // gram n-splits

// ---------------- scratch (device globals; no runtime allocation) ----------
static __device__ float g_q[(size_t)MTOT * CC];
static __device__ float g_k[(size_t)MTOT * CC];
static __device__ float g_v[(size_t)MTOT * CC];      // illu-gated values
static __device__ float g_vinp[(size_t)MTOT * CC];   // raw x@Wv (conv branch)
static __device__ float g_t1[(size_t)MTOT * CC];     // conv intermediate
static __device__ float g_weff[(size_t)BB * CC * CC];
static __device__ float g_partq[BB * NCHUNK * CC];
static __device__ float g_partk[BB * NCHUNK * CC];
static __device__ float g_invq[BB * CC];
static __device__ float g_invk[BB * CC];
static __device__ float g_gpart[(size_t)GSPLIT * BB * NHEAD * DHEAD * DHEAD];
static __device__ float g_attn[(size_t)BB * NHEAD * DHEAD * DHEAD];

// ---------------- 128x128x8 fp32 SGEMM, 256 threads, 8x8 per thread --------
// MODE 0: C = A@B
// MODE 1: C2 = A@B (raw), C = raw * illu   (elementwise gate, same layout)
// MODE 2: C = A@B + bias[col]
template <int MODE>
__global__ void __launch_bounds__(256) sgemm128(
    const float* __restrict__ A, const float* __restrict__ Bw,
    float* __restrict__ C, float* __restrict__ C2,
    const float* __restrict__ illu, const float* __restrict__ bias,
    int K, int Ncols, size_t sA, size_t sB, size_t sC)
{
    __shared__ float As[8][128];
    __shared__ float Bs[8][128];

    int bz = blockIdx.z;
    A += (size_t)bz * sA;
    Bw += (size_t)bz * sB;
    C += (size_t)bz * sC;

    const float* Ab = A + (size_t)blockIdx.y * 128 * K;
    const float* Bb = Bw + blockIdx.x * 128;

    int tid = threadIdx.x;
    int arow = tid >> 1;            // 0..127
    int acol = (tid & 1) * 4;       // 0 or 4
    int brow = tid >> 5;            // 0..7
    int bcol = (tid & 31) * 4;      // 0..124
    int ty = tid >> 4, tx = tid & 15;

    float acc[8][8];
#pragma unroll
    for (int i = 0; i < 8; i++)
#pragma unroll
        for (int j = 0; j < 8; j++) acc[i][j] = 0.f;

    for (int k0 = 0; k0 < K; k0 += 8) {
        float4 av = *(const float4*)(Ab + (size_t)arow * K + k0 + acol);
        As[acol + 0][arow] = av.x;
        As[acol + 1][arow] = av.y;
        As[acol + 2][arow] = av.z;
        As[acol + 3][arow] = av.w;
        float4 bv = *(const float4*)(Bb + (size_t)(k0 + brow) * Ncols + bcol);
        *(float4*)(&Bs[brow][bcol]) = bv;
        __syncthreads();
#pragma unroll
        for (int kk = 0; kk < 8; kk++) {
            float a[8], b[8];
            *(float4*)(a)     = *(const float4*)(&As[kk][ty * 8]);
            *(float4*)(a + 4) = *(const float4*)(&As[kk][ty * 8 + 4]);
            *(float4*)(b)     = *(const float4*)(&Bs[kk][tx * 8]);
            *(float4*)(b + 4) = *(const float4*)(&Bs[kk][tx * 8 + 4]);
#pragma unroll
            for (int i = 0; i < 8; i++)
#pragma unroll
                for (int j = 0; j < 8; j++)
                    acc[i][j] += a[i] * b[j];
        }
        __syncthreads();
    }

    size_t rowbase = (size_t)blockIdx.y * 128 + ty * 8;
    int colbase = blockIdx.x * 128 + tx * 8;
#pragma unroll
    for (int i = 0; i < 8; i++) {
        size_t off = (rowbase + i) * Ncols + colbase;
        if (MODE == 0) {
            *(float4*)(C + off)     = *(float4*)(&acc[i][0]);
            *(float4*)(C + off + 4) = *(float4*)(&acc[i][4]);
        } else if (MODE == 1) {
#pragma unroll
            for (int j = 0; j < 8; j++) {
                float raw = acc[i][j];
                C2[off + j] = raw;
                C[off + j] = raw * illu[off + j];
            }
        } else {
#pragma unroll
            for (int j = 0; j < 8; j++)
                C[off + j] = acc[i][j] + bias[colbase + j];
        }
    }
}

// ------------- column sum-of-squares partials (coalesced, no atomics) -------
__global__ void colsumsq(const float* __restrict__ X, float* __restrict__ part)
{
    int c = threadIdx.x;            // 0..511
    int chunk = blockIdx.x;         // 0..31
    int b = blockIdx.y;
    const float* p = X + ((size_t)b * NTOK + (size_t)chunk * 512) * CC + c;
    float acc = 0.f;
#pragma unroll 8
    for (int r = 0; r < 512; r++) {
        float v = p[(size_t)r * CC];
        acc += v * v;
    }
    part[(b * NCHUNK + chunk) * CC + c] = acc;
}

__global__ void invnorm(const float* __restrict__ pq, const float* __restrict__ pk,
                        float* __restrict__ iq, float* __restrict__ ik)
{
    int c = threadIdx.x, b = blockIdx.x;
    float sq = 0.f, sk = 0.f;
#pragma unroll
    for (int i = 0; i < NCHUNK; i++) {
        sq += pq[(b * NCHUNK + i) * CC + c];
        sk += pk[(b * NCHUNK + i) * CC + c];
    }
    iq[b * CC + c] = 1.f / fmaxf(sqrtf(sq), 1e-12f);
    ik[b * CC + c] = 1.f / fmaxf(sqrtf(sk), 1e-12f);
}

// ------------- Gram: G[d,e] = sum_n K[n, h*64+d] * Q[n, h*64+e] -------------
__global__ void __launch_bounds__(256) gram_kernel(
    const float* __restrict__ Q, const float* __restrict__ Kx,
    float* __restrict__ part)
{
    __shared__ float Ks[64][64];
    __shared__ float Qs[64][64];
    int h = blockIdx.x, b = blockIdx.y, s = blockIdx.z;
    int tid = threadIdx.x;
    int ty = tid >> 4, tx = tid & 15;

    size_t base = (size_t)b * NTOK * CC + h * DHEAD;
    int n_begin = s * (NTOK / GSPLIT);

    float acc[4][4];
#pragma unroll
    for (int i = 0; i < 4; i++)
#pragma unroll
        for (int j = 0; j < 4; j++) acc[i][j] = 0.f;

    for (int n0 = n_begin; n0 < n_begin + NTOK / GSPLIT; n0 += 64) {
        for (int idx = tid; idx < 64 * 16; idx += 256) {
            int nl = idx >> 4;
            int f = (idx & 15) * 4;
            size_t g = base + (size_t)(n0 + nl) * CC + f;
            *(float4*)(&Ks[nl][f]) = *(const float4*)(Kx + g);
            *(float4*)(&Qs[nl][f]) = *(const float4*)(Q + g);
        }
        __syncthreads();
#pragma unroll 8
        for (int n = 0; n < 64; n++) {
            float a[4], bq[4];
            *(float4*)a  = *(const float4*)(&Ks[n][ty * 4]);
            *(float4*)bq = *(const float4*)(&Qs[n][tx * 4]);
#pragma unroll
            for (int i = 0; i < 4; i++)
#pragma unroll
                for (int j = 0; j < 4; j++)
                    acc[i][j] += a[i] * bq[j];
        }
        __syncthreads();
    }

    float* dst = part + (((size_t)s * BB + b) * NHEAD + h) * (DHEAD * DHEAD);
#pragma unroll
    for (int i = 0; i < 4; i++)
#pragma unroll
        for (int j = 0; j < 4; j++)
            dst[(ty * 4 + i) * DHEAD + tx * 4 + j] = acc[i][j];
}

// ------------- reduce splits + normalize + rescale + softmax over e ---------
__global__ void softmax_kernel(const float* __restrict__ part,
                               const float* __restrict__ iq,
                               const float* __restrict__ ik,
                               const float* __restrict__ rescale,
                               float* __restrict__ attn)
{
    int bh = blockIdx.x;
    int b = bh / NHEAD, h = bh % NHEAD;
    int d = threadIdx.x;  // 0..63

    __shared__ float iq_s[64];
    iq_s[d] = iq[b * CC + h * DHEAD + d];
    float ik_d = ik[b * CC + h * DHEAD + d];
    float resc = rescale[h];
    __syncthreads();

    float row[64];
    float m = -1e30f;
#pragma unroll
    for (int e = 0; e < 64; e++) {
        float s = 0.f;
#pragma unroll
        for (int sp = 0; sp < GSPLIT; sp++)
            s += part[(((size_t)sp * BB + b) * NHEAD + h) * 4096 + d * 64 + e];
        float lg = s * ik_d * iq_s[e] * resc;
        row[e] = lg;
        m = fmaxf(m, lg);
    }
    float sum = 0.f;
#pragma unroll
    for (int e = 0; e < 64; e++) {
        row[e] = __expf(row[e] - m);
        sum += row[e];
    }
    float inv = 1.f / sum;
    float* dst = attn + ((size_t)(b * NHEAD + h)) * 4096 + d * 64;
#pragma unroll
    for (int e = 0; e < 64; e++) dst[e] = row[e] * inv;
}

// ------------- Weff[b][h*64+e][j] = sum_d attn[b,h,d,e] * Wp[h*64+d][j] -----
__global__ void weff_kernel(const float* __restrict__ attn,
                            const float* __restrict__ Wp,
                            float* __restrict__ weff)
{
    int eg = blockIdx.x;   // 0..511
    int b = blockIdx.y;
    int tid = threadIdx.x;
    int h = eg >> 6, e = eg & 63;

    __shared__ float a_s[64];
    if (tid < 64) a_s[tid] = attn[((size_t)(b * NHEAD + h) * 64 + tid) * 64 + e];
    __syncthreads();

    for (int j = tid; j < CC; j += 256) {
        float acc = 0.f;
#pragma unroll
        for (int d = 0; d < 64; d++)
            acc += a_s[d] * Wp[(size_t)(h * 64 + d) * CC + j];
        weff[((size_t)b * CC + eg) * CC + j] = acc;
    }
}

// ------------- depthwise 3x3 conv (NHWC), SAME padding ---------------------
// ADD==0: out = gelu_exact(conv(in));  ADD==1: out += conv(in)
template <int ADD>
__global__ void dwconv3(const float* __restrict__ in,
                        const float* __restrict__ w9,
                        float* __restrict__ out)
{
    size_t idx = (size_t)blockIdx.x * blockDim.x + threadIdx.x;
    int ch = (int)(idx & 511);
    int x = (int)((idx >> 9) & 127);
    int y = (int)((idx >> 16) & 127);
    int b = (int)(idx >> 23);

    float wv[9];
#pragma unroll
    for (int t = 0; t < 9; t++) wv[t] = w9[ch * 9 + t];

    float acc = 0.f;
#pragma unroll
    for (int dy = -1; dy <= 1; dy++) {
        int yy = y + dy;
        if (yy < 0 || yy > 127) continue;
#pragma unroll
        for (int dx = -1; dx <= 1; dx++) {
            int xx = x + dx;
            if (xx < 0 || xx > 127) continue;
            acc += in[(((size_t)b * HH + yy) * WW + xx) * CC + ch] *
                   wv[(dy + 1) * 3 + (dx + 1)];
        }
    }
    if (ADD) {
        out[idx] += acc;
    } else {
        // exact GELU: 0.5*x*(1+erf(x/sqrt(2)))
        out[idx] = 0.5f * acc * (1.f + erff(acc * 0.70710678118654752f));
    }
}

// ---------------------------------------------------------------------------
extern "C" void kernel_launch(void* const* d_in, const int* in_sizes, int n_in,
                              void* d_out, int out_size)
{
    const float* x    = (const float*)d_in[0];
    const float* illu = (const float*)d_in[1];
    const float* Wq   = (const float*)d_in[2];
    const float* Wk   = (const float*)d_in[3];
    const float* Wv   = (const float*)d_in[4];
    const float* resc = (const float*)d_in[5];
    const float* Wp   = (const float*)d_in[6];
    const float* bp   = (const float*)d_in[7];
    const float* c1w  = (const float*)d_in[8];
    const float* c2w  = (const float*)d_in[9];
    float* out = (float*)d_out;

    float *q, *k, *v, *vinp, *t1, *weff, *pq, *pk, *iq, *ik, *gp, *attn;
    cudaGetSymbolAddress((void**)&q, g_q);
    cudaGetSymbolAddress((void**)&k, g_k);
    cudaGetSymbolAddress((void**)&v, g_v);
    cudaGetSymbolAddress((void**)&vinp, g_vinp);
    cudaGetSymbolAddress((void**)&t1, g_t1);
    cudaGetSymbolAddress((void**)&weff, g_weff);
    cudaGetSymbolAddress((void**)&pq, g_partq);
    cudaGetSymbolAddress((void**)&pk, g_partk);
    cudaGetSymbolAddress((void**)&iq, g_invq);
    cudaGetSymbolAddress((void**)&ik, g_invk);
    cudaGetSymbolAddress((void**)&gp, g_gpart);
    cudaGetSymbolAddress((void**)&attn, g_attn);

    // 1) projections: Q, K, V(+gate, raw copy for conv branch)
    dim3 gProj(CC / 128, MTOT / 128, 1);
    sgemm128<0><<<gProj, 256>>>(x, Wq, q, nullptr, nullptr, nullptr, CC, CC, 0, 0, 0);
    sgemm128<0><<<gProj, 256>>>(x, Wk, k, nullptr, nullptr, nullptr, CC, CC, 0, 0, 0);
    sgemm128<1><<<gProj, 256>>>(x, Wv, v, vinp, illu, nullptr, CC, CC, 0, 0, 0);

    // 2) per-(b,channel) L2 norms of q,k over tokens
    colsumsq<<<dim3(NCHUNK, BB), 512>>>(q, pq);
    colsumsq<<<dim3(NCHUNK, BB), 512>>>(k, pk);
    invnorm<<<BB, 512>>>(pq, pk, iq, ik);

    // 3) Gram matrices + softmax -> attn[b,h,64,64]
    gram_kernel<<<dim3(NHEAD, BB, GSPLIT), 256>>>(q, k, gp);
    softmax_kernel<<<BB * NHEAD, 64>>>(gp, iq, ik, resc, attn);

    // 4) fold attention into projection weight: Weff_b = blockdiag(attn)^T @ Wp
    weff_kernel<<<dim3(CC, BB), 256>>>(attn, Wp, weff);

    // 5) out_c = V @ Weff_b + bp   (batched GEMM)
    sgemm128<2><<<dim3(CC / 128, NTOK / 128, BB), 256>>>(
        v, weff, out, nullptr, nullptr, bp, CC, CC,
        (size_t)NTOK * CC, (size_t)CC * CC, (size_t)NTOK * CC);

    // 6) positional branch: dwconv -> gelu -> dwconv, added to out
    size_t total = (size_t)MTOT * CC;
    int blocks = (int)(total / 256);
    dwconv3<0><<<blocks, 256>>>(vinp, c1w, t1);
    dwconv3<1><<<blocks, 256>>>(t1, c2w, out);
}

// round 4
// speedup vs baseline: 1.8879x; 1.8879x over previous
#include <cuda_runtime.h>
#include <cuda_bf16.h>
#include <math.h>
#include <stdint.h>

// Problem constants
#define BB 4
#define HH 128
#define WW 128
#define CC 512
#define NTOK 16384            // H*W
#define NHEAD 8
#define DHEAD 64
#define MTOT (BB*NTOK)        // 65536
#define NCHUNK 32
#define GSPLIT 8

// ---------------- scratch (device globals; no runtime allocation) ----------
static __device__ float g_q[(size_t)MTOT * CC];
static __device__ float g_k[(size_t)MTOT * CC];
static __device__ float g_v[(size_t)MTOT * CC];      // illu-gated values
static __device__ float g_vinp[(size_t)MTOT * CC];   // raw x@Wv (conv branch)
static __device__ float g_t1[(size_t)MTOT * CC];     // conv intermediate
static __device__ float g_weff[(size_t)BB * CC * CC];
static __device__ float g_wefft[(size_t)BB * CC * CC];
static __device__ float g_wT[3 * CC * CC];           // WqT, WkT, WvT
static __device__ float g_partq[BB * NCHUNK * CC];
static __device__ float g_partk[BB * NCHUNK * CC];
static __device__ float g_invq[BB * CC];
static __device__ float g_invk[BB * CC];
static __device__ float g_gpart[(size_t)GSPLIT * BB * NHEAD * DHEAD * DHEAD];
static __device__ float g_attn[(size_t)BB * NHEAD * DHEAD * DHEAD];

// =================== helpers ==============================================
__device__ __forceinline__ uint32_t s2u(const void* p) {
    uint32_t a;
    asm("{ .reg .u64 t; cvta.to.shared.u64 t, %1; cvt.u32.u64 %0, t; }"
        : "=r"(a) : "l"(p));
    return a;
}

// split 2 floats -> packed bf16 hi pair and lo pair (low half = first arg)
__device__ __forceinline__ void cvt2(float a, float b, uint32_t& h, uint32_t& l) {
    uint32_t hp;
    asm("cvt.rn.bf16x2.f32 %0, %1, %2;" : "=r"(hp) : "f"(b), "f"(a));
    float ah = __uint_as_float(hp << 16);
    float bh = __uint_as_float(hp & 0xFFFF0000u);
    float al = a - ah;
    float bl = b - bh;
    uint32_t lp;
    asm("cvt.rn.bf16x2.f32 %0, %1, %2;" : "=r"(lp) : "f"(bl), "f"(al));
    h = hp; l = lp;
}

__device__ __forceinline__ void ldm_x4(uint32_t* r, uint32_t addr) {
    asm volatile("ldmatrix.sync.aligned.m8n8.x4.shared.b16 {%0,%1,%2,%3}, [%4];"
                 : "=r"(r[0]), "=r"(r[1]), "=r"(r[2]), "=r"(r[3]) : "r"(addr));
}
__device__ __forceinline__ void ldm_x2(uint32_t* r, uint32_t addr) {
    asm volatile("ldmatrix.sync.aligned.m8n8.x2.shared.b16 {%0,%1}, [%2];"
                 : "=r"(r[0]), "=r"(r[1]) : "r"(addr));
}
__device__ __forceinline__ void mma16816(float* c, const uint32_t* a, const uint32_t* b) {
    asm volatile(
        "mma.sync.aligned.m16n8k16.row.col.f32.bf16.bf16.f32 "
        "{%0,%1,%2,%3}, {%4,%5,%6,%7}, {%8,%9}, {%0,%1,%2,%3};"
        : "+f"(c[0]), "+f"(c[1]), "+f"(c[2]), "+f"(c[3])
        : "r"(a[0]), "r"(a[1]), "r"(a[2]), "r"(a[3]), "r"(b[0]), "r"(b[1]));
}

// =================== mma.sync GEMM: C[M,512] = A[M,512] @ Bt[512,512]^T ====
// A row-major [M,512] fp32; Bt row-major [N,K] fp32 (pre-transposed weights).
// CTA: 128x128 tile, 8 warps (warp tile 64x32), K chunks of 32, hi/lo bf16
// split (3 HMMA passes per k16), fp32 accum in registers.
// Smem: 4 matrices [128 rows][80 bytes] (32 bf16 + 16B pad): Ahi,Alo,Bhi,Blo.
// MODE 0: C = A@B ; MODE 1: C2 = A@B, C = (A@B)*illu ; MODE 2: C = A@B + bias
#define ROWB 80
#define MAT_BYTES (128 * ROWB)      // 10240
#define GEMM_SMEM (4 * MAT_BYTES + 1024)

template <int MODE>
__global__ void __launch_bounds__(256, 2) gemm_mma(
    const float* __restrict__ A, const float* __restrict__ Bt,
    float* __restrict__ C, float* __restrict__ C2,
    const float* __restrict__ illu, const float* __restrict__ bias,
    size_t sA, size_t sB, size_t sC)
{
    extern __shared__ char dyn[];
    const int tid = threadIdx.x;
    const int wid = tid >> 5, lane = tid & 31;
    const int wm = wid & 1, wn = wid >> 1;

    const int bz = blockIdx.z;
    A += (size_t)bz * sA;
    Bt += (size_t)bz * sB;
    C += (size_t)bz * sC;
    const size_t row0 = (size_t)blockIdx.y * 128;
    const int n0 = blockIdx.x * 128;

    uint32_t sbase = s2u(dyn);
    sbase = (sbase + 1023u) & ~1023u;
    char* sb = dyn + (sbase - s2u(dyn));
    const uint32_t aHi = sbase;
    const uint32_t aLo = sbase + MAT_BYTES;
    const uint32_t bHi = sbase + 2 * MAT_BYTES;
    const uint32_t bLo = sbase + 3 * MAT_BYTES;

    float acc[4][4][4];
#pragma unroll
    for (int i = 0; i < 4; i++)
#pragma unroll
        for (int j = 0; j < 4; j++)
#pragma unroll
            for (int t = 0; t < 4; t++) acc[i][j][t] = 0.f;

    // per-thread staging assignment: unit u = tid; r = u>>1, seg = u&1
    const int lr = tid >> 1;         // 0..127
    const int lseg = tid & 1;        // 0..1 (16 fp32 each)

    // ldmatrix addresses (byte offsets within a matrix)
    const int a_row = wm * 64 + (lane & 15);
    const int a_koff = (lane >> 4) * 16;          // 0 or 16 bytes (k +8)
    const int b_row = wn * 32 + (lane & 7);
    const int b_koff = ((lane >> 3) & 1) * 16;

    for (int ch = 0; ch < 16; ch++) {
        const int k0 = ch * 32;
        // ---- stage chunk: fp32 -> bf16 hi/lo into smem ----
        {
            const float* Ap = A + (row0 + lr) * CC + k0 + lseg * 16;
            const float* Bp = Bt + (size_t)(n0 + lr) * CC + k0 + lseg * 16;
            float4 a0 = *(const float4*)(Ap + 0);
            float4 a1 = *(const float4*)(Ap + 4);
            float4 a2 = *(const float4*)(Ap + 8);
            float4 a3 = *(const float4*)(Ap + 12);
            float4 b0 = *(const float4*)(Bp + 0);
            float4 b1 = *(const float4*)(Bp + 4);
            float4 b2 = *(const float4*)(Bp + 8);
            float4 b3 = *(const float4*)(Bp + 12);
            uint4 h0, l0, h1, l1;
            cvt2(a0.x, a0.y, h0.x, l0.x); cvt2(a0.z, a0.w, h0.y, l0.y);
            cvt2(a1.x, a1.y, h0.z, l0.z); cvt2(a1.z, a1.w, h0.w, l0.w);
            cvt2(a2.x, a2.y, h1.x, l1.x); cvt2(a2.z, a2.w, h1.y, l1.y);
            cvt2(a3.x, a3.y, h1.z, l1.z); cvt2(a3.z, a3.w, h1.w, l1.w);
            int off = lr * ROWB + lseg * 32;
            *(uint4*)(sb + off) = h0;
            *(uint4*)(sb + off + 16) = h1;
            *(uint4*)(sb + MAT_BYTES + off) = l0;
            *(uint4*)(sb + MAT_BYTES + off + 16) = l1;
            cvt2(b0.x, b0.y, h0.x, l0.x); cvt2(b0.z, b0.w, h0.y, l0.y);
            cvt2(b1.x, b1.y, h0.z, l0.z); cvt2(b1.z, b1.w, h0.w, l0.w);
            cvt2(b2.x, b2.y, h1.x, l1.x); cvt2(b2.z, b2.w, h1.y, l1.y);
            cvt2(b3.x, b3.y, h1.z, l1.z); cvt2(b3.z, b3.w, h1.w, l1.w);
            *(uint4*)(sb + 2 * MAT_BYTES + off) = h0;
            *(uint4*)(sb + 2 * MAT_BYTES + off + 16) = h1;
            *(uint4*)(sb + 3 * MAT_BYTES + off) = l0;
            *(uint4*)(sb + 3 * MAT_BYTES + off + 16) = l1;
        }
        __syncthreads();

        // ---- compute: 2 k16 steps, 3 split passes each ----
#pragma unroll
        for (int ks = 0; ks < 2; ks++) {
            const int kb = ks * 32;  // byte offset of this k16 within row
            uint32_t ah[4][4], al[4][4], bh[4][2], bl[4][2];
#pragma unroll
            for (int i = 0; i < 4; i++) {
                uint32_t ra = (a_row + i * 16) * ROWB + kb + a_koff;
                ldm_x4(ah[i], aHi + ra);
                ldm_x4(al[i], aLo + ra);
            }
#pragma unroll
            for (int j = 0; j < 4; j++) {
                uint32_t rb = (b_row + j * 8) * ROWB + kb + b_koff;
                ldm_x2(bh[j], bHi + rb);
                ldm_x2(bl[j], bLo + rb);
            }
#pragma unroll
            for (int i = 0; i < 4; i++)
#pragma unroll
                for (int j = 0; j < 4; j++) {
                    mma16816(acc[i][j], ah[i], bh[j]);
                    mma16816(acc[i][j], ah[i], bl[j]);
                    mma16816(acc[i][j], al[i], bh[j]);
                }
        }
        __syncthreads();
    }

    // ---- epilogue ----
    const int mrow = wm * 64 + (lane >> 2);
    const int mcol = n0 + wn * 32 + (lane & 3) * 2;
#pragma unroll
    for (int i = 0; i < 4; i++) {
#pragma unroll
        for (int half = 0; half < 2; half++) {
            size_t r = row0 + mrow + i * 16 + half * 8;
            size_t base = r * CC + mcol;
#pragma unroll
            for (int j = 0; j < 4; j++) {
                float2 v2;
                v2.x = acc[i][j][half * 2 + 0];
                v2.y = acc[i][j][half * 2 + 1];
                size_t off = base + j * 8;
                if (MODE == 0) {
                    *(float2*)(C + off) = v2;
                } else if (MODE == 1) {
                    float2 iv = *(const float2*)(illu + off);
                    *(float2*)(C2 + off) = v2;
                    float2 gv; gv.x = v2.x * iv.x; gv.y = v2.y * iv.y;
                    *(float2*)(C + off) = gv;
                } else {
                    float2 bv = *(const float2*)(bias + mcol + j * 8);
                    v2.x += bv.x; v2.y += bv.y;
                    *(float2*)(C + off) = v2;
                }
            }
        }
    }
}

// =================== 512x512 transpose (batched via z) ======================
__global__ void transpose512(const float* __restrict__ src, float* __restrict__ dst)
{
    __shared__ float t[32][33];
    size_t bo = (size_t)blockIdx.z * (CC * CC);
    int x = blockIdx.x * 32 + threadIdx.x;
    int y0 = blockIdx.y * 32;
    for (int j = threadIdx.y; j < 32; j += 8)
        t[j][threadIdx.x] = src[bo + (size_t)(y0 + j) * CC + x];
    __syncthreads();
    int xo = blockIdx.y * 32 + threadIdx.x;
    int yo0 = blockIdx.x * 32;
    for (int j = threadIdx.y; j < 32; j += 8)
        dst[bo + (size_t)(yo0 + j) * CC + xo] = t[threadIdx.x][j];
}

// ------------- column sum-of-squares partials ------------------------------
__global__ void colsumsq(const float* __restrict__ X, float* __restrict__ part)
{
    int c = threadIdx.x;
    int chunk = blockIdx.x;
    int b = blockIdx.y;
    const float* p = X + ((size_t)b * NTOK + (size_t)chunk * 512) * CC + c;
    float acc = 0.f;
#pragma unroll 8
    for (int r = 0; r < 512; r++) {
        float v = p[(size_t)r * CC];
        acc += v * v;
    }
    part[(b * NCHUNK + chunk) * CC + c] = acc;
}

__global__ void invnorm(const float* __restrict__ pq, const float* __restrict__ pk,
                        float* __restrict__ iq, float* __restrict__ ik)
{
    int c = threadIdx.x, b = blockIdx.x;
    float sq = 0.f, sk = 0.f;
#pragma unroll
    for (int i = 0; i < NCHUNK; i++) {
        sq += pq[(b * NCHUNK + i) * CC + c];
        sk += pk[(b * NCHUNK + i) * CC + c];
    }
    iq[b * CC + c] = 1.f / fmaxf(sqrtf(sq), 1e-12f);
    ik[b * CC + c] = 1.f / fmaxf(sqrtf(sk), 1e-12f);
}

// ------------- Gram: G[d,e] = sum_n K[n, h*64+d] * Q[n, h*64+e] -------------
__global__ void __launch_bounds__(256) gram_kernel(
    const float* __restrict__ Q, const float* __restrict__ Kx,
    float* __restrict__ part)
{
    __shared__ float Ks[64][64];
    __shared__ float Qs[64][64];
    int h = blockIdx.x, b = blockIdx.y, s = blockIdx.z;
    int tid = threadIdx.x;
    int ty = tid >> 4, tx = tid & 15;

    size_t base = (size_t)b * NTOK * CC + h * DHEAD;
    int n_begin = s * (NTOK / GSPLIT);

    float acc[4][4];
#pragma unroll
    for (int i = 0; i < 4; i++)
#pragma unroll
        for (int j = 0; j < 4; j++) acc[i][j] = 0.f;

    for (int n0 = n_begin; n0 < n_begin + NTOK / GSPLIT; n0 += 64) {
        for (int idx = tid; idx < 64 * 16; idx += 256) {
            int nl = idx >> 4;
            int f = (idx & 15) * 4;
            size_t g = base + (size_t)(n0 + nl) * CC + f;
            *(float4*)(&Ks[nl][f]) = *(const float4*)(Kx + g);
            *(float4*)(&Qs[nl][f]) = *(const float4*)(Q + g);
        }
        __syncthreads();
#pragma unroll 8
        for (int n = 0; n < 64; n++) {
            float a[4], bq[4];
            *(float4*)a  = *(const float4*)(&Ks[n][ty * 4]);
            *(float4*)bq = *(const float4*)(&Qs[n][tx * 4]);
#pragma unroll
            for (int i = 0; i < 4; i++)
#pragma unroll
                for (int j = 0; j < 4; j++)
                    acc[i][j] += a[i] * bq[j];
        }
        __syncthreads();
    }

    float* dst = part + (((size_t)s * BB + b) * NHEAD + h) * (DHEAD * DHEAD);
#pragma unroll
    for (int i = 0; i < 4; i++)
#pragma unroll
        for (int j = 0; j < 4; j++)
            dst[(ty * 4 + i) * DHEAD + tx * 4 + j] = acc[i][j];
}

// ------------- softmax over e ----------------------------------------------
__global__ void softmax_kernel(const float* __restrict__ part,
                               const float* __restrict__ iq,
                               const float* __restrict__ ik,
                               const float* __restrict__ rescale,
                               float* __restrict__ attn)
{
    int bh = blockIdx.x;
    int b = bh / NHEAD, h = bh % NHEAD;
    int d = threadIdx.x;

    __shared__ float iq_s[64];
    iq_s[d] = iq[b * CC + h * DHEAD + d];
    float ik_d = ik[b * CC + h * DHEAD + d];
    float resc = rescale[h];
    __syncthreads();

    float row[64];
    float m = -1e30f;
#pragma unroll
    for (int e = 0; e < 64; e++) {
        float s = 0.f;
#pragma unroll
        for (int sp = 0; sp < GSPLIT; sp++)
            s += part[(((size_t)sp * BB + b) * NHEAD + h) * 4096 + d * 64 + e];
        float lg = s * ik_d * iq_s[e] * resc;
        row[e] = lg;
        m = fmaxf(m, lg);
    }
    float sum = 0.f;
#pragma unroll
    for (int e = 0; e < 64; e++) {
        row[e] = __expf(row[e] - m);
        sum += row[e];
    }
    float inv = 1.f / sum;
    float* dst = attn + ((size_t)(b * NHEAD + h)) * 4096 + d * 64;
#pragma unroll
    for (int e = 0; e < 64; e++) dst[e] = row[e] * inv;
}

// ------------- Weff[b][h*64+e][j] = sum_d attn[b,h,d,e] * Wp[h*64+d][j] -----
__global__ void weff_kernel(const float* __restrict__ attn,
                            const float* __restrict__ Wp,
                            float* __restrict__ weff)
{
    int eg = blockIdx.x;
    int b = blockIdx.y;
    int tid = threadIdx.x;
    int h = eg >> 6, e = eg & 63;

    __shared__ float a_s[64];
    if (tid < 64) a_s[tid] = attn[((size_t)(b * NHEAD + h) * 64 + tid) * 64 + e];
    __syncthreads();

    for (int j = tid; j < CC; j += 256) {
        float acc = 0.f;
#pragma unroll
        for (int d = 0; d < 64; d++)
            acc += a_s[d] * Wp[(size_t)(h * 64 + d) * CC + j];
        weff[((size_t)b * CC + eg) * CC + j] = acc;
    }
}

// ------------- depthwise 3x3 conv (NHWC), SAME padding ---------------------
template <int ADD>
__global__ void dwconv3(const float* __restrict__ in,
                        const float* __restrict__ w9,
                        float* __restrict__ out)
{
    size_t idx = (size_t)blockIdx.x * blockDim.x + threadIdx.x;
    int ch = (int)(idx & 511);
    int x = (int)((idx >> 9) & 127);
    int y = (int)((idx >> 16) & 127);
    int b = (int)(idx >> 23);

    float wv[9];
#pragma unroll
    for (int t = 0; t < 9; t++) wv[t] = w9[ch * 9 + t];

    float acc = 0.f;
#pragma unroll
    for (int dy = -1; dy <= 1; dy++) {
        int yy = y + dy;
        if (yy < 0 || yy > 127) continue;
#pragma unroll
        for (int dx = -1; dx <= 1; dx++) {
            int xx = x + dx;
            if (xx < 0 || xx > 127) continue;
            acc += in[(((size_t)b * HH + yy) * WW + xx) * CC + ch] *
                   wv[(dy + 1) * 3 + (dx + 1)];
        }
    }
    if (ADD) {
        out[idx] += acc;
    } else {
        out[idx] = 0.5f * acc * (1.f + erff(acc * 0.70710678118654752f));
    }
}

// ---------------------------------------------------------------------------
extern "C" void kernel_launch(void* const* d_in, const int* in_sizes, int n_in,
                              void* d_out, int out_size)
{
    const float* x    = (const float*)d_in[0];
    const float* illu = (const float*)d_in[1];
    const float* Wq   = (const float*)d_in[2];
    const float* Wk   = (const float*)d_in[3];
    const float* Wv   = (const float*)d_in[4];
    const float* resc = (const float*)d_in[5];
    const float* Wp   = (const float*)d_in[6];
    const float* bp   = (const float*)d_in[7];
    const float* c1w  = (const float*)d_in[8];
    const float* c2w  = (const float*)d_in[9];
    float* out = (float*)d_out;

    float *q, *k, *v, *vinp, *t1, *weff, *wefft, *wT, *pq, *pk, *iq, *ik, *gp, *attn;
    cudaGetSymbolAddress((void**)&q, g_q);
    cudaGetSymbolAddress((void**)&k, g_k);
    cudaGetSymbolAddress((void**)&v, g_v);
    cudaGetSymbolAddress((void**)&vinp, g_vinp);
    cudaGetSymbolAddress((void**)&t1, g_t1);
    cudaGetSymbolAddress((void**)&weff, g_weff);
    cudaGetSymbolAddress((void**)&wefft, g_wefft);
    cudaGetSymbolAddress((void**)&wT, g_wT);
    cudaGetSymbolAddress((void**)&pq, g_partq);
    cudaGetSymbolAddress((void**)&pk, g_partk);
    cudaGetSymbolAddress((void**)&iq, g_invq);
    cudaGetSymbolAddress((void**)&ik, g_invk);
    cudaGetSymbolAddress((void**)&gp, g_gpart);
    cudaGetSymbolAddress((void**)&attn, g_attn);

    cudaFuncSetAttribute(gemm_mma<0>, cudaFuncAttributeMaxDynamicSharedMemorySize, GEMM_SMEM);
    cudaFuncSetAttribute(gemm_mma<1>, cudaFuncAttributeMaxDynamicSharedMemorySize, GEMM_SMEM);
    cudaFuncSetAttribute(gemm_mma<2>, cudaFuncAttributeMaxDynamicSharedMemorySize, GEMM_SMEM);

    // 0) pre-transpose weights to [N,K]
    dim3 tb(32, 8);
    transpose512<<<dim3(16, 16, 1), tb>>>(Wq, wT);
    transpose512<<<dim3(16, 16, 1), tb>>>(Wk, wT + CC * CC);
    transpose512<<<dim3(16, 16, 1), tb>>>(Wv, wT + 2 * CC * CC);

    // 1) projections on tensor pipe (hi/lo bf16 split, fp32 accuracy class)
    dim3 gProj(CC / 128, MTOT / 128, 1);
    gemm_mma<0><<<gProj, 256, GEMM_SMEM>>>(x, wT, q, nullptr, nullptr, nullptr, 0, 0, 0);
    gemm_mma<0><<<gProj, 256, GEMM_SMEM>>>(x, wT + CC * CC, k, nullptr, nullptr, nullptr, 0, 0, 0);
    gemm_mma<1><<<gProj, 256, GEMM_SMEM>>>(x, wT + 2 * CC * CC, v, vinp, illu, nullptr, 0, 0, 0);

    // 2) per-(b,channel) L2 norms of q,k over tokens
    colsumsq<<<dim3(NCHUNK, BB), 512>>>(q, pq);
    colsumsq<<<dim3(NCHUNK, BB), 512>>>(k, pk);
    invnorm<<<BB, 512>>>(pq, pk, iq, ik);

    // 3) Gram + softmax -> attn[b,h,64,64]
    gram_kernel<<<dim3(NHEAD, BB, GSPLIT), 256>>>(q, k, gp);
    softmax_kernel<<<BB * NHEAD, 64>>>(gp, iq, ik, resc, attn);

    // 4) fold attention into projection weight, then transpose to [N,K]
    weff_kernel<<<dim3(CC, BB), 256>>>(attn, Wp, weff);
    transpose512<<<dim3(16, 16, BB), tb>>>(weff, wefft);

    // 5) out_c = V @ Weff_b + bp  (batched, tensor pipe)
    gemm_mma<2><<<dim3(CC / 128, NTOK / 128, BB), 256, GEMM_SMEM>>>(
        v, wefft, out, nullptr, nullptr, bp,
        (size_t)NTOK * CC, (size_t)CC * CC, (size_t)NTOK * CC);

    // 6) positional branch: dwconv -> gelu -> dwconv, added to out
    size_t total = (size_t)MTOT * CC;
    int blocks = (int)(total / 256);
    dwconv3<0><<<blocks, 256>>>(vinp, c1w, t1);
    dwconv3<1><<<blocks, 256>>>(t1, c2w, out);
}

// round 5
// speedup vs baseline: 1.9221x; 1.0181x over previous
#include <cuda_runtime.h>
#include <cuda_bf16.h>
#include <math.h>
#include <stdint.h>

// Problem constants
#define BB 4
#define HH 128
#define WW 128
#define CC 512
#define NTOK 16384            // H*W
#define NHEAD 8
#define DHEAD 64
#define MTOT (BB*NTOK)        // 65536
#define NCHUNK 32
#define GSPLIT 8              // gram n-splits (CTA level); x8 warps = 64 partials
#define GS_TOT 64

typedef __nv_bfloat16 bf16;

// ---------------- scratch (device globals; no runtime allocation) ----------
static __device__ float g_q[(size_t)MTOT * CC];
static __device__ float g_k[(size_t)MTOT * CC];
static __device__ float g_vinp[(size_t)MTOT * CC];   // raw x@Wv (conv branch)
static __device__ float g_t1[(size_t)MTOT * CC];     // conv intermediate
static __device__ float g_weff[(size_t)BB * CC * CC];

static __device__ __align__(16) bf16 g_xhi[(size_t)MTOT * CC];
static __device__ __align__(16) bf16 g_xlo[(size_t)MTOT * CC];
static __device__ __align__(16) bf16 g_vhi[(size_t)MTOT * CC];
static __device__ __align__(16) bf16 g_vlo[(size_t)MTOT * CC];
static __device__ __align__(16) bf16 g_wThi[3 * CC * CC];
static __device__ __align__(16) bf16 g_wTlo[3 * CC * CC];
static __device__ __align__(16) bf16 g_wfhi[(size_t)BB * CC * CC];
static __device__ __align__(16) bf16 g_wflo[(size_t)BB * CC * CC];
static __device__ __align__(16) bf16 g_qthi[(size_t)BB * CC * NTOK];
static __device__ __align__(16) bf16 g_qtlo[(size_t)BB * CC * NTOK];
static __device__ __align__(16) bf16 g_kthi[(size_t)BB * CC * NTOK];
static __device__ __align__(16) bf16 g_ktlo[(size_t)BB * CC * NTOK];

static __device__ float g_partq[BB * NCHUNK * CC];
static __device__ float g_partk[BB * NCHUNK * CC];
static __device__ float g_invq[BB * CC];
static __device__ float g_invk[BB * CC];
static __device__ float g_gpart[(size_t)GS_TOT * BB * NHEAD * DHEAD * DHEAD];
static __device__ float g_attn[(size_t)BB * NHEAD * DHEAD * DHEAD];

// =================== helpers ==============================================
__device__ __forceinline__ uint32_t s2u(const void* p) {
    uint32_t a;
    asm("{ .reg .u64 t; cvta.to.shared.u64 t, %1; cvt.u32.u64 %0, t; }"
        : "=r"(a) : "l"(p));
    return a;
}

// split 2 floats -> packed bf16 hi pair and lo pair (low half = first arg)
__device__ __forceinline__ void cvt2(float a, float b, uint32_t& h, uint32_t& l) {
    uint32_t hp;
    asm("cvt.rn.bf16x2.f32 %0, %1, %2;" : "=r"(hp) : "f"(b), "f"(a));
    float ah = __uint_as_float(hp << 16);
    float bh = __uint_as_float(hp & 0xFFFF0000u);
    float al = a - ah;
    float bl = b - bh;
    uint32_t lp;
    asm("cvt.rn.bf16x2.f32 %0, %1, %2;" : "=r"(lp) : "f"(bl), "f"(al));
    h = hp; l = lp;
}

__device__ __forceinline__ void split1(float f, uint16_t& h, uint16_t& l) {
    uint32_t hp;
    asm("cvt.rn.bf16x2.f32 %0, %1, %2;" : "=r"(hp) : "f"(0.f), "f"(f));
    float hf = __uint_as_float(hp << 16);
    float lf = f - hf;
    uint32_t lp;
    asm("cvt.rn.bf16x2.f32 %0, %1, %2;" : "=r"(lp) : "f"(0.f), "f"(lf));
    h = (uint16_t)hp; l = (uint16_t)lp;
}

__device__ __forceinline__ void ldm_x4(uint32_t* r, uint32_t addr) {
    asm volatile("ldmatrix.sync.aligned.m8n8.x4.shared.b16 {%0,%1,%2,%3}, [%4];"
                 : "=r"(r[0]), "=r"(r[1]), "=r"(r[2]), "=r"(r[3]) : "r"(addr));
}
__device__ __forceinline__ void ldm_x2(uint32_t* r, uint32_t addr) {
    asm volatile("ldmatrix.sync.aligned.m8n8.x2.shared.b16 {%0,%1}, [%2];"
                 : "=r"(r[0]), "=r"(r[1]) : "r"(addr));
}
__device__ __forceinline__ void mma16816(float* c, const uint32_t* a, const uint32_t* b) {
    asm volatile(
        "mma.sync.aligned.m16n8k16.row.col.f32.bf16.bf16.f32 "
        "{%0,%1,%2,%3}, {%4,%5,%6,%7}, {%8,%9}, {%0,%1,%2,%3};"
        : "+f"(c[0]), "+f"(c[1]), "+f"(c[2]), "+f"(c[3])
        : "r"(a[0]), "r"(a[1]), "r"(a[2]), "r"(a[3]), "r"(b[0]), "r"(b[1]));
}
__device__ __forceinline__ void cp16(uint32_t dst, const void* src) {
    asm volatile("cp.async.cg.shared.global [%0], [%1], 16;" :: "r"(dst), "l"(src));
}

// =================== conversion kernels ====================================
// x fp32 -> xhi, xlo bf16 (same layout), 8 elems/thread
__global__ void cvt_x(const float* __restrict__ x, bf16* __restrict__ xhi,
                      bf16* __restrict__ xlo)
{
    size_t g = ((size_t)blockIdx.x * 256 + threadIdx.x);
    const float4* p = (const float4*)(x + g * 8);
    float4 a = p[0], b = p[1];
    uint4 h, l;
    cvt2(a.x, a.y, h.x, l.x); cvt2(a.z, a.w, h.y, l.y);
    cvt2(b.x, b.y, h.z, l.z); cvt2(b.z, b.w, h.w, l.w);
    ((uint4*)xhi)[g] = h;
    ((uint4*)xlo)[g] = l;
}

// transpose + convert: src fp32 [R][512] (batched) -> dst bf16 [512][R] hi/lo
__global__ void tcvt(const float* __restrict__ src, bf16* __restrict__ dhi,
                     bf16* __restrict__ dlo, int R, size_t sStride, size_t dStride)
{
    __shared__ uint16_t shh[32][65];
    __shared__ uint16_t shl[32][65];
    int z = blockIdx.z;
    const float* s = src + (size_t)z * sStride;
    int c = blockIdx.y * 32 + threadIdx.x;
    int nb = blockIdx.x * 64;
#pragma unroll
    for (int i = 0; i < 8; i++) {
        int n = threadIdx.y + i * 8;
        float f = s[(size_t)(nb + n) * CC + c];
        uint16_t h, l;
        split1(f, h, l);
        shh[threadIdx.x][n] = h;
        shl[threadIdx.x][n] = l;
    }
    __syncthreads();
#pragma unroll
    for (int i = 0; i < 4; i++) {
        int cl = threadIdx.y + i * 8;
        int row = blockIdx.y * 32 + cl;
        size_t u32idx = ((size_t)row * R + nb) >> 1;
        uint32_t h = (uint32_t)shh[cl][threadIdx.x * 2] |
                     ((uint32_t)shh[cl][threadIdx.x * 2 + 1] << 16);
        uint32_t l = (uint32_t)shl[cl][threadIdx.x * 2] |
                     ((uint32_t)shl[cl][threadIdx.x * 2 + 1] << 16);
        ((uint32_t*)(dhi + (size_t)z * dStride))[u32idx + threadIdx.x] = h;
        ((uint32_t*)(dlo + (size_t)z * dStride))[u32idx + threadIdx.x] = l;
    }
}

// =================== pipelined bf16 GEMM ===================================
// C[M,512] = A[M,512] @ Bt[512,512]^T, A/B given as bf16 hi/lo (3-term split).
// CTA 128x128, 8 warps (64x32 each), k-chunk 32, 2-stage cp.async pipeline.
// MODE 0: C = A@B (fp32)
// MODE 1: C2 = raw fp32; Vhi/Vlo = bf16 split of raw*illu
// MODE 2: C = A@B + bias
#define KCH 32
#define ROWB 80
#define MATB (128 * ROWB)        // 10240
#define STAGEB (4 * MATB)        // 40960
#define GEMM_SMEM (2 * STAGEB)   // 81920

__device__ __forceinline__ void stage_issue(
    uint32_t sb, int tid,
    const bf16* a0, const bf16* a1, const bf16* b0, const bf16* b1)
{
    const bf16* g[4] = {a0, a1, b0, b1};
#pragma unroll
    for (int m = 0; m < 4; m++) {
#pragma unroll
        for (int it = 0; it < 2; it++) {
            int s2 = tid + it * 256;
            int r = s2 >> 2, seg = s2 & 3;
            cp16(sb + m * MATB + r * ROWB + seg * 16,
                 g[m] + (size_t)r * CC + seg * 8);
        }
    }
    asm volatile("cp.async.commit_group;" ::: "memory");
}

template <int MODE>
__global__ void __launch_bounds__(256, 2) gemm_bf(
    const bf16* __restrict__ Ahi, const bf16* __restrict__ Alo,
    const bf16* __restrict__ Bhi, const bf16* __restrict__ Blo,
    float* __restrict__ C, float* __restrict__ C2,
    bf16* __restrict__ Vhi, bf16* __restrict__ Vlo,
    const float* __restrict__ illu, const float* __restrict__ bias,
    size_t zRow, size_t sB)
{
    extern __shared__ char smem[];
    const uint32_t sb0 = s2u(smem);
    const int tid = threadIdx.x;
    const int wid = tid >> 5, lane = tid & 31;
    const int wm = wid & 1, wn = wid >> 1;

    const size_t row0 = (size_t)blockIdx.y * 128 + (size_t)blockIdx.z * zRow;
    const int n0 = blockIdx.x * 128;
    const size_t boff = (size_t)blockIdx.z * sB + (size_t)n0 * CC;

    float acc[4][4][4];
#pragma unroll
    for (int i = 0; i < 4; i++)
#pragma unroll
        for (int j = 0; j < 4; j++)
#pragma unroll
            for (int t = 0; t < 4; t++) acc[i][j][t] = 0.f;

    const int a_row = wm * 64 + (lane & 15);
    const int a_koff = (lane >> 4) * 16;
    const int b_row = wn * 32 + (lane & 7);
    const int b_koff = ((lane >> 3) & 1) * 16;

    stage_issue(sb0, tid, Ahi + row0 * CC, Alo + row0 * CC,
                Bhi + boff, Blo + boff);
    stage_issue(sb0 + STAGEB, tid, Ahi + row0 * CC + KCH, Alo + row0 * CC + KCH,
                Bhi + boff + KCH, Blo + boff + KCH);

    for (int ch = 0; ch < 16; ch++) {
        const int cur = ch & 1;
        if (ch < 15) asm volatile("cp.async.wait_group 1;" ::: "memory");
        else         asm volatile("cp.async.wait_group 0;" ::: "memory");
        __syncthreads();

        const uint32_t base = sb0 + cur * STAGEB;
        const uint32_t aHi = base, aLo = base + MATB;
        const uint32_t bHi = base + 2 * MATB, bLo = base + 3 * MATB;
#pragma unroll
        for (int ks = 0; ks < 2; ks++) {
            const int kb = ks * 32;
            uint32_t ah[4][4], al[4][4], bh[4][2], bl[4][2];
#pragma unroll
            for (int i = 0; i < 4; i++) {
                uint32_t ra = (a_row + i * 16) * ROWB + kb + a_koff;
                ldm_x4(ah[i], aHi + ra);
                ldm_x4(al[i], aLo + ra);
            }
#pragma unroll
            for (int j = 0; j < 4; j++) {
                uint32_t rb = (b_row + j * 8) * ROWB + kb + b_koff;
                ldm_x2(bh[j], bHi + rb);
                ldm_x2(bl[j], bLo + rb);
            }
#pragma unroll
            for (int i = 0; i < 4; i++)
#pragma unroll
                for (int j = 0; j < 4; j++) {
                    mma16816(acc[i][j], ah[i], bh[j]);
                    mma16816(acc[i][j], ah[i], bl[j]);
                    mma16816(acc[i][j], al[i], bh[j]);
                }
        }
        __syncthreads();
        if (ch + 2 < 16) {
            const int k0 = (ch + 2) * KCH;
            stage_issue(base, tid, Ahi + row0 * CC + k0, Alo + row0 * CC + k0,
                        Bhi + boff + k0, Blo + boff + k0);
        }
    }

    // ---- epilogue ----
    const int mrow = wm * 64 + (lane >> 2);
    const int mcol = n0 + wn * 32 + (lane & 3) * 2;
#pragma unroll
    for (int i = 0; i < 4; i++) {
#pragma unroll
        for (int half = 0; half < 2; half++) {
            size_t r = row0 + mrow + i * 16 + half * 8;
            size_t base = r * CC + mcol;
#pragma unroll
            for (int j = 0; j < 4; j++) {
                float2 v2;
                v2.x = acc[i][j][half * 2 + 0];
                v2.y = acc[i][j][half * 2 + 1];
                size_t off = base + j * 8;
                if (MODE == 0) {
                    *(float2*)(C + off) = v2;
                } else if (MODE == 1) {
                    float2 iv = *(const float2*)(illu + off);
                    *(float2*)(C2 + off) = v2;
                    uint32_t h, l;
                    cvt2(v2.x * iv.x, v2.y * iv.y, h, l);
                    ((uint32_t*)Vhi)[off >> 1] = h;
                    ((uint32_t*)Vlo)[off >> 1] = l;
                } else {
                    float2 bv = *(const float2*)(bias + mcol + j * 8);
                    v2.x += bv.x; v2.y += bv.y;
                    *(float2*)(C + off) = v2;
                }
            }
        }
    }
}

// ------------- column sum-of-squares partials ------------------------------
__global__ void colsumsq(const float* __restrict__ X, float* __restrict__ part)
{
    int c = threadIdx.x;
    int chunk = blockIdx.x;
    int b = blockIdx.y;
    const float* p = X + ((size_t)b * NTOK + (size_t)chunk * 512) * CC + c;
    float acc = 0.f;
#pragma unroll 8
    for (int r = 0; r < 512; r++) {
        float v = p[(size_t)r * CC];
        acc += v * v;
    }
    part[(b * NCHUNK + chunk) * CC + c] = acc;
}

__global__ void invnorm(const float* __restrict__ pq, const float* __restrict__ pk,
                        float* __restrict__ iq, float* __restrict__ ik)
{
    int c = threadIdx.x, b = blockIdx.x;
    float sq = 0.f, sk = 0.f;
#pragma unroll
    for (int i = 0; i < NCHUNK; i++) {
        sq += pq[(b * NCHUNK + i) * CC + c];
        sk += pk[(b * NCHUNK + i) * CC + c];
    }
    iq[b * CC + c] = 1.f / fmaxf(sqrtf(sq), 1e-12f);
    ik[b * CC + c] = 1.f / fmaxf(sqrtf(sk), 1e-12f);
}

// ------------- Gram via mma with direct-LDG fragments ----------------------
// G[d,e] = sum_n KT[d,n] * QT[e,n], per (b,h); partials over 64 n-splits.
__global__ void __launch_bounds__(256) gram_mma(
    const bf16* __restrict__ KThi, const bf16* __restrict__ KTlo,
    const bf16* __restrict__ QThi, const bf16* __restrict__ QTlo,
    float* __restrict__ part)
{
    const int h = blockIdx.x, b = blockIdx.y, s = blockIdx.z;
    const int wid = threadIdx.x >> 5, lane = threadIdx.x & 31;
    const int nbase = s * (NTOK / GSPLIT) + wid * 256;

    const size_t rowbase = ((size_t)b * CC + h * DHEAD) * NTOK;
    const bf16* Kh = KThi + rowbase;
    const bf16* Kl = KTlo + rowbase;
    const bf16* Qh = QThi + rowbase;
    const bf16* Ql = QTlo + rowbase;

    float acc[4][8][4];
#pragma unroll
    for (int i = 0; i < 4; i++)
#pragma unroll
        for (int j = 0; j < 8; j++)
#pragma unroll
            for (int t = 0; t < 4; t++) acc[i][j][t] = 0.f;

    const int rsel = lane >> 2;
    const int csel = (lane & 3) * 2;

    for (int step = 0; step < 16; step++) {
        const int nb = nbase + step * 16 + csel;
        uint32_t ah[4][4], al[4][4];
#pragma unroll
        for (int mt = 0; mt < 4; mt++) {
            const size_t r0 = (size_t)(mt * 16 + rsel) * NTOK;
            const size_t r8 = r0 + 8 * NTOK;
            ah[mt][0] = *(const uint32_t*)(Kh + r0 + nb);
            ah[mt][1] = *(const uint32_t*)(Kh + r8 + nb);
            ah[mt][2] = *(const uint32_t*)(Kh + r0 + nb + 8);
            ah[mt][3] = *(const uint32_t*)(Kh + r8 + nb + 8);
            al[mt][0] = *(const uint32_t*)(Kl + r0 + nb);
            al[mt][1] = *(const uint32_t*)(Kl + r8 + nb);
            al[mt][2] = *(const uint32_t*)(Kl + r0 + nb + 8);
            al[mt][3] = *(const uint32_t*)(Kl + r8 + nb + 8);
        }
#pragma unroll
        for (int nt = 0; nt < 8; nt++) {
            const size_t q0 = (size_t)(nt * 8 + rsel) * NTOK;
            uint32_t bh[2], bl[2];
            bh[0] = *(const uint32_t*)(Qh + q0 + nb);
            bh[1] = *(const uint32_t*)(Qh + q0 + nb + 8);
            bl[0] = *(const uint32_t*)(Ql + q0 + nb);
            bl[1] = *(const uint32_t*)(Ql + q0 + nb + 8);
#pragma unroll
            for (int mt = 0; mt < 4; mt++) {
                mma16816(acc[mt][nt], ah[mt], bh);
                mma16816(acc[mt][nt], ah[mt], bl);
                mma16816(acc[mt][nt], al[mt], bh);
            }
        }
    }

    const int sp = s * 8 + wid;
    float* dst = part + (((size_t)sp * BB + b) * NHEAD + h) * 4096;
#pragma unroll
    for (int mt = 0; mt < 4; mt++)
#pragma unroll
        for (int nt = 0; nt < 8; nt++) {
            int r = mt * 16 + rsel, c = nt * 8 + csel;
            dst[r * 64 + c]           = acc[mt][nt][0];
            dst[r * 64 + c + 1]       = acc[mt][nt][1];
            dst[(r + 8) * 64 + c]     = acc[mt][nt][2];
            dst[(r + 8) * 64 + c + 1] = acc[mt][nt][3];
        }
}

// ------------- softmax over e ----------------------------------------------
__global__ void softmax_kernel(const float* __restrict__ part,
                               const float* __restrict__ iq,
                               const float* __restrict__ ik,
                               const float* __restrict__ rescale,
                               float* __restrict__ attn)
{
    int bh = blockIdx.x;
    int b = bh / NHEAD, h = bh % NHEAD;
    int d = threadIdx.x;

    __shared__ float iq_s[64];
    iq_s[d] = iq[b * CC + h * DHEAD + d];
    float ik_d = ik[b * CC + h * DHEAD + d];
    float resc = rescale[h];
    __syncthreads();

    float row[64];
#pragma unroll
    for (int e = 0; e < 64; e++) row[e] = 0.f;
    for (int sp = 0; sp < GS_TOT; sp++) {
        const float* p = part + (((size_t)sp * BB + b) * NHEAD + h) * 4096 + d * 64;
#pragma unroll 8
        for (int e = 0; e < 64; e++) row[e] += p[e];
    }
    float m = -1e30f;
#pragma unroll
    for (int e = 0; e < 64; e++) {
        row[e] = row[e] * ik_d * iq_s[e] * resc;
        m = fmaxf(m, row[e]);
    }
    float sum = 0.f;
#pragma unroll
    for (int e = 0; e < 64; e++) {
        row[e] = __expf(row[e] - m);
        sum += row[e];
    }
    float inv = 1.f / sum;
    float* dst = attn + ((size_t)(b * NHEAD + h)) * 4096 + d * 64;
#pragma unroll
    for (int e = 0; e < 64; e++) dst[e] = row[e] * inv;
}

// ------------- Weff[b][h*64+e][j] = sum_d attn[b,h,d,e] * Wp[h*64+d][j] -----
__global__ void weff_kernel(const float* __restrict__ attn,
                            const float* __restrict__ Wp,
                            float* __restrict__ weff)
{
    int eg = blockIdx.x;
    int b = blockIdx.y;
    int tid = threadIdx.x;
    int h = eg >> 6, e = eg & 63;

    __shared__ float a_s[64];
    if (tid < 64) a_s[tid] = attn[((size_t)(b * NHEAD + h) * 64 + tid) * 64 + e];
    __syncthreads();

    for (int j = tid; j < CC; j += 256) {
        float acc = 0.f;
#pragma unroll
        for (int d = 0; d < 64; d++)
            acc += a_s[d] * Wp[(size_t)(h * 64 + d) * CC + j];
        weff[((size_t)b * CC + eg) * CC + j] = acc;
    }
}

// ------------- depthwise 3x3 conv (NHWC), SAME padding ---------------------
template <int ADD>
__global__ void dwconv3(const float* __restrict__ in,
                        const float* __restrict__ w9,
                        float* __restrict__ out)
{
    size_t idx = (size_t)blockIdx.x * blockDim.x + threadIdx.x;
    int ch = (int)(idx & 511);
    int x = (int)((idx >> 9) & 127);
    int y = (int)((idx >> 16) & 127);
    int b = (int)(idx >> 23);

    float wv[9];
#pragma unroll
    for (int t = 0; t < 9; t++) wv[t] = w9[ch * 9 + t];

    float acc = 0.f;
#pragma unroll
    for (int dy = -1; dy <= 1; dy++) {
        int yy = y + dy;
        if (yy < 0 || yy > 127) continue;
#pragma unroll
        for (int dx = -1; dx <= 1; dx++) {
            int xx = x + dx;
            if (xx < 0 || xx > 127) continue;
            acc += in[(((size_t)b * HH + yy) * WW + xx) * CC + ch] *
                   wv[(dy + 1) * 3 + (dx + 1)];
        }
    }
    if (ADD) {
        out[idx] += acc;
    } else {
        out[idx] = 0.5f * acc * (1.f + erff(acc * 0.70710678118654752f));
    }
}

// ---------------------------------------------------------------------------
extern "C" void kernel_launch(void* const* d_in, const int* in_sizes, int n_in,
                              void* d_out, int out_size)
{
    const float* x    = (const float*)d_in[0];
    const float* illu = (const float*)d_in[1];
    const float* Wq   = (const float*)d_in[2];
    const float* Wk   = (const float*)d_in[3];
    const float* Wv   = (const float*)d_in[4];
    const float* resc = (const float*)d_in[5];
    const float* Wp   = (const float*)d_in[6];
    const float* bp   = (const float*)d_in[7];
    const float* c1w  = (const float*)d_in[8];
    const float* c2w  = (const float*)d_in[9];
    float* out = (float*)d_out;

    float *q, *k, *vinp, *t1, *weff, *pq, *pk, *iq, *ik, *gp, *attn;
    bf16 *xhi, *xlo, *vhi, *vlo, *wThi, *wTlo, *wfhi, *wflo;
    bf16 *qthi, *qtlo, *kthi, *ktlo;
    cudaGetSymbolAddress((void**)&q, g_q);
    cudaGetSymbolAddress((void**)&k, g_k);
    cudaGetSymbolAddress((void**)&vinp, g_vinp);
    cudaGetSymbolAddress((void**)&t1, g_t1);
    cudaGetSymbolAddress((void**)&weff, g_weff);
    cudaGetSymbolAddress((void**)&pq, g_partq);
    cudaGetSymbolAddress((void**)&pk, g_partk);
    cudaGetSymbolAddress((void**)&iq, g_invq);
    cudaGetSymbolAddress((void**)&ik, g_invk);
    cudaGetSymbolAddress((void**)&gp, g_gpart);
    cudaGetSymbolAddress((void**)&attn, g_attn);
    cudaGetSymbolAddress((void**)&xhi, g_xhi);
    cudaGetSymbolAddress((void**)&xlo, g_xlo);
    cudaGetSymbolAddress((void**)&vhi, g_vhi);
    cudaGetSymbolAddress((void**)&vlo, g_vlo);
    cudaGetSymbolAddress((void**)&wThi, g_wThi);
    cudaGetSymbolAddress((void**)&wTlo, g_wTlo);
    cudaGetSymbolAddress((void**)&wfhi, g_wfhi);
    cudaGetSymbolAddress((void**)&wflo, g_wflo);
    cudaGetSymbolAddress((void**)&qthi, g_qthi);
    cudaGetSymbolAddress((void**)&qtlo, g_qtlo);
    cudaGetSymbolAddress((void**)&kthi, g_kthi);
    cudaGetSymbolAddress((void**)&ktlo, g_ktlo);

    cudaFuncSetAttribute(gemm_bf<0>, cudaFuncAttributeMaxDynamicSharedMemorySize, GEMM_SMEM);
    cudaFuncSetAttribute(gemm_bf<1>, cudaFuncAttributeMaxDynamicSharedMemorySize, GEMM_SMEM);
    cudaFuncSetAttribute(gemm_bf<2>, cudaFuncAttributeMaxDynamicSharedMemorySize, GEMM_SMEM);

    // 0) conversions: x -> bf16 hi/lo; weights -> transposed bf16 hi/lo
    cvt_x<<<(int)((size_t)MTOT * CC / (256 * 8)), 256>>>(x, xhi, xlo);
    dim3 tb(32, 8);
    tcvt<<<dim3(8, 16, 1), tb>>>(Wq, wThi, wTlo, CC, 0, 0);
    tcvt<<<dim3(8, 16, 1), tb>>>(Wk, wThi + CC * CC, wTlo + CC * CC, CC, 0, 0);
    tcvt<<<dim3(8, 16, 1), tb>>>(Wv, wThi + 2 * CC * CC, wTlo + 2 * CC * CC, CC, 0, 0);

    // 1) projections (pipelined bf16 tensor GEMM)
    dim3 gProj(CC / 128, MTOT / 128, 1);
    gemm_bf<0><<<gProj, 256, GEMM_SMEM>>>(xhi, xlo, wThi, wTlo,
        q, nullptr, nullptr, nullptr, nullptr, nullptr, 0, 0);
    gemm_bf<0><<<gProj, 256, GEMM_SMEM>>>(xhi, xlo, wThi + CC * CC, wTlo + CC * CC,
        k, nullptr, nullptr, nullptr, nullptr, nullptr, 0, 0);
    gemm_bf<1><<<gProj, 256, GEMM_SMEM>>>(xhi, xlo, wThi + 2 * CC * CC, wTlo + 2 * CC * CC,
        nullptr, vinp, vhi, vlo, illu, nullptr, 0, 0);

    // 2) L2 norms of q,k over tokens
    colsumsq<<<dim3(NCHUNK, BB), 512>>>(q, pq);
    colsumsq<<<dim3(NCHUNK, BB), 512>>>(k, pk);
    invnorm<<<BB, 512>>>(pq, pk, iq, ik);

    // 3) transpose-convert q,k -> [b][c][n] bf16 hi/lo; gram on tensor pipe
    tcvt<<<dim3(NTOK / 64, 16, BB), tb>>>(q, qthi, qtlo, NTOK,
        (size_t)NTOK * CC, (size_t)CC * NTOK);
    tcvt<<<dim3(NTOK / 64, 16, BB), tb>>>(k, kthi, ktlo, NTOK,
        (size_t)NTOK * CC, (size_t)CC * NTOK);
    gram_mma<<<dim3(NHEAD, BB, GSPLIT), 256>>>(kthi, ktlo, qthi, qtlo, gp);
    softmax_kernel<<<BB * NHEAD, 64>>>(gp, iq, ik, resc, attn);

    // 4) fold attention into Wp; transpose-convert to bf16 [n][k]
    weff_kernel<<<dim3(CC, BB), 256>>>(attn, Wp, weff);
    tcvt<<<dim3(8, 16, BB), tb>>>(weff, wfhi, wflo, CC,
        (size_t)CC * CC, (size_t)CC * CC);

    // 5) out_c = V @ Weff_b + bp (batched)
    gemm_bf<2><<<dim3(CC / 128, NTOK / 128, BB), 256, GEMM_SMEM>>>(
        vhi, vlo, wfhi, wflo, out, nullptr, nullptr, nullptr, nullptr, bp,
        (size_t)NTOK, (size_t)CC * CC);

    // 6) positional branch: dwconv -> gelu -> dwconv, added to out
    size_t total = (size_t)MTOT * CC;
    int blocks = (int)(total / 256);
    dwconv3<0><<<blocks, 256>>>(vinp, c1w, t1);
    dwconv3<1><<<blocks, 256>>>(t1, c2w, out);
}

// round 6
// speedup vs baseline: 2.1159x; 1.1008x over previous
#include <cuda_runtime.h>
#include <cuda_bf16.h>
#include <math.h>
#include <stdint.h>

// Problem constants
#define BB 4
#define HH 128
#define WW 128
#define CC 512
#define NTOK 16384            // H*W
#define NHEAD 8
#define DHEAD 64
#define MTOT (BB*NTOK)        // 65536
#define GSPLIT 8              // gram n-splits (CTA level); x8 warps = 64 partials
#define GS_TOT 64

typedef __nv_bfloat16 bf16;

// ---------------- scratch (device globals; no runtime allocation) ----------
static __device__ float g_vinp[(size_t)MTOT * CC];   // raw x@Wv (conv branch)
static __device__ float g_weff[(size_t)BB * CC * CC];

static __device__ __align__(16) bf16 g_xhi[(size_t)MTOT * CC];
static __device__ __align__(16) bf16 g_xlo[(size_t)MTOT * CC];
static __device__ __align__(16) bf16 g_vhi[(size_t)MTOT * CC];
static __device__ __align__(16) bf16 g_vlo[(size_t)MTOT * CC];
static __device__ __align__(16) bf16 g_wThi[3 * CC * CC];
static __device__ __align__(16) bf16 g_wTlo[3 * CC * CC];
static __device__ __align__(16) bf16 g_wfhi[(size_t)BB * CC * CC];
static __device__ __align__(16) bf16 g_wflo[(size_t)BB * CC * CC];
static __device__ __align__(16) bf16 g_qthi[(size_t)BB * CC * NTOK];
static __device__ __align__(16) bf16 g_qtlo[(size_t)BB * CC * NTOK];
static __device__ __align__(16) bf16 g_kthi[(size_t)BB * CC * NTOK];
static __device__ __align__(16) bf16 g_ktlo[(size_t)BB * CC * NTOK];

static __device__ float g_invq[BB * CC];
static __device__ float g_invk[BB * CC];
static __device__ float g_gpart[(size_t)GS_TOT * BB * NHEAD * DHEAD * DHEAD];
static __device__ float g_attn[(size_t)BB * NHEAD * DHEAD * DHEAD];

// =================== helpers ==============================================
__device__ __forceinline__ uint32_t s2u(const void* p) {
    uint32_t a;
    asm("{ .reg .u64 t; cvta.to.shared.u64 t, %1; cvt.u32.u64 %0, t; }"
        : "=r"(a) : "l"(p));
    return a;
}

// split 2 floats -> packed bf16 hi pair and lo pair (low half = first arg)
__device__ __forceinline__ void cvt2(float a, float b, uint32_t& h, uint32_t& l) {
    uint32_t hp;
    asm("cvt.rn.bf16x2.f32 %0, %1, %2;" : "=r"(hp) : "f"(b), "f"(a));
    float ah = __uint_as_float(hp << 16);
    float bh = __uint_as_float(hp & 0xFFFF0000u);
    float al = a - ah;
    float bl = b - bh;
    uint32_t lp;
    asm("cvt.rn.bf16x2.f32 %0, %1, %2;" : "=r"(lp) : "f"(bl), "f"(al));
    h = hp; l = lp;
}

__device__ __forceinline__ void split1(float f, uint16_t& h, uint16_t& l) {
    uint32_t hp;
    asm("cvt.rn.bf16x2.f32 %0, %1, %2;" : "=r"(hp) : "f"(0.f), "f"(f));
    float hf = __uint_as_float(hp << 16);
    float lf = f - hf;
    uint32_t lp;
    asm("cvt.rn.bf16x2.f32 %0, %1, %2;" : "=r"(lp) : "f"(0.f), "f"(lf));
    h = (uint16_t)hp; l = (uint16_t)lp;
}

__device__ __forceinline__ float bfu16_to_f(uint32_t u) {
    return __uint_as_float(u << 16);
}

__device__ __forceinline__ void ldm_x4(uint32_t* r, uint32_t addr) {
    asm volatile("ldmatrix.sync.aligned.m8n8.x4.shared.b16 {%0,%1,%2,%3}, [%4];"
                 : "=r"(r[0]), "=r"(r[1]), "=r"(r[2]), "=r"(r[3]) : "r"(addr));
}
__device__ __forceinline__ void mma16816(float* c, const uint32_t* a, const uint32_t* b) {
    asm volatile(
        "mma.sync.aligned.m16n8k16.row.col.f32.bf16.bf16.f32 "
        "{%0,%1,%2,%3}, {%4,%5,%6,%7}, {%8,%9}, {%0,%1,%2,%3};"
        : "+f"(c[0]), "+f"(c[1]), "+f"(c[2]), "+f"(c[3])
        : "r"(a[0]), "r"(a[1]), "r"(a[2]), "r"(a[3]), "r"(b[0]), "r"(b[1]));
}
__device__ __forceinline__ void cp16(uint32_t dst, const void* src) {
    asm volatile("cp.async.cg.shared.global [%0], [%1], 16;" :: "r"(dst), "l"(src));
}

// =================== conversion kernels ====================================
__global__ void cvt_x(const float* __restrict__ x, bf16* __restrict__ xhi,
                      bf16* __restrict__ xlo)
{
    size_t g = ((size_t)blockIdx.x * 256 + threadIdx.x);
    const float4* p = (const float4*)(x + g * 8);
    float4 a = p[0], b = p[1];
    uint4 h, l;
    cvt2(a.x, a.y, h.x, l.x); cvt2(a.z, a.w, h.y, l.y);
    cvt2(b.x, b.y, h.z, l.z); cvt2(b.z, b.w, h.w, l.w);
    ((uint4*)xhi)[g] = h;
    ((uint4*)xlo)[g] = l;
}

// transpose + convert: src fp32 [R][512] (batched) -> dst bf16 [512][R] hi/lo
__global__ void tcvt(const float* __restrict__ src, bf16* __restrict__ dhi,
                     bf16* __restrict__ dlo, int R, size_t sStride, size_t dStride)
{
    __shared__ uint16_t shh[32][65];
    __shared__ uint16_t shl[32][65];
    int z = blockIdx.z;
    const float* s = src + (size_t)z * sStride;
    int c = blockIdx.y * 32 + threadIdx.x;
    int nb = blockIdx.x * 64;
#pragma unroll
    for (int i = 0; i < 8; i++) {
        int n = threadIdx.y + i * 8;
        float f = s[(size_t)(nb + n) * CC + c];
        uint16_t h, l;
        split1(f, h, l);
        shh[threadIdx.x][n] = h;
        shl[threadIdx.x][n] = l;
    }
    __syncthreads();
#pragma unroll
    for (int i = 0; i < 4; i++) {
        int cl = threadIdx.y + i * 8;
        int row = blockIdx.y * 32 + cl;
        size_t u32idx = ((size_t)row * R + nb) >> 1;
        uint32_t h = (uint32_t)shh[cl][threadIdx.x * 2] |
                     ((uint32_t)shh[cl][threadIdx.x * 2 + 1] << 16);
        uint32_t l = (uint32_t)shl[cl][threadIdx.x * 2] |
                     ((uint32_t)shl[cl][threadIdx.x * 2 + 1] << 16);
        ((uint32_t*)(dhi + (size_t)z * dStride))[u32idx + threadIdx.x] = h;
        ((uint32_t*)(dlo + (size_t)z * dStride))[u32idx + threadIdx.x] = l;
    }
}

// =================== pipelined bf16 GEMM ===================================
// C[M,512] = A[M,512] @ Bt[512,512]^T, A/B bf16 hi/lo (3-term split).
// CTA 128x128, 8 warps (64x32), k-chunk 32, 2-stage cp.async pipeline.
// MODE 1: C2 = raw fp32; Vhi/Vlo = bf16 split of raw*illu
// MODE 2: C = A@B + bias
// MODE 3: transposed bf16 hi/lo output: Vhi/Vlo[b][col][row] (for q,k)
#define KCH 32
#define ROWB 80
#define MATB (128 * ROWB)        // 10240
#define STAGEB (4 * MATB)        // 40960
#define GEMM_SMEM (2 * STAGEB)   // 81920

__device__ __forceinline__ void stage_issue(
    uint32_t sb, int tid,
    const bf16* a0, const bf16* a1, const bf16* b0, const bf16* b1)
{
    const bf16* g[4] = {a0, a1, b0, b1};
#pragma unroll
    for (int m = 0; m < 4; m++) {
#pragma unroll
        for (int it = 0; it < 2; it++) {
            int s2 = tid + it * 256;
            int r = s2 >> 2, seg = s2 & 3;
            cp16(sb + m * MATB + r * ROWB + seg * 16,
                 g[m] + (size_t)r * CC + seg * 8);
        }
    }
    asm volatile("cp.async.commit_group;" ::: "memory");
}

template <int MODE>
__global__ void __launch_bounds__(256, 2) gemm_bf(
    const bf16* __restrict__ Ahi, const bf16* __restrict__ Alo,
    const bf16* __restrict__ Bhi, const bf16* __restrict__ Blo,
    float* __restrict__ C, float* __restrict__ C2,
    bf16* __restrict__ Vhi, bf16* __restrict__ Vlo,
    const float* __restrict__ illu, const float* __restrict__ bias,
    size_t zRow, size_t sB)
{
    extern __shared__ char smem[];
    const uint32_t sb0 = s2u(smem);
    const int tid = threadIdx.x;
    const int wid = tid >> 5, lane = tid & 31;
    const int wm = wid & 1, wn = wid >> 1;

    const size_t row0 = (size_t)blockIdx.y * 128 + (size_t)blockIdx.z * zRow;
    const int n0 = blockIdx.x * 128;
    const size_t boff = (size_t)blockIdx.z * sB + (size_t)n0 * CC;

    float acc[4][4][4];
#pragma unroll
    for (int i = 0; i < 4; i++)
#pragma unroll
        for (int j = 0; j < 4; j++)
#pragma unroll
            for (int t = 0; t < 4; t++) acc[i][j][t] = 0.f;

    const int a_row = wm * 64 + (lane & 15);
    const int a_koff = (lane >> 4) * 16;
    // B x4 addressing: mat = lane>>3; col block = mat>>1, k half = mat&1
    const int b_row4 = wn * 32 + ((lane >> 4) & 1) * 8 + (lane & 7);
    const int b_koff4 = ((lane >> 3) & 1) * 16;

    stage_issue(sb0, tid, Ahi + row0 * CC, Alo + row0 * CC,
                Bhi + boff, Blo + boff);
    stage_issue(sb0 + STAGEB, tid, Ahi + row0 * CC + KCH, Alo + row0 * CC + KCH,
                Bhi + boff + KCH, Blo + boff + KCH);

    for (int ch = 0; ch < 16; ch++) {
        const int cur = ch & 1;
        if (ch < 15) asm volatile("cp.async.wait_group 1;" ::: "memory");
        else         asm volatile("cp.async.wait_group 0;" ::: "memory");
        __syncthreads();

        const uint32_t base = sb0 + cur * STAGEB;
        const uint32_t aHi = base, aLo = base + MATB;
        const uint32_t bHi = base + 2 * MATB, bLo = base + 3 * MATB;
#pragma unroll
        for (int ks = 0; ks < 2; ks++) {
            const int kb = ks * 32;
            uint32_t ah[4][4], al[4][4], bh[4][2], bl[4][2];
#pragma unroll
            for (int i = 0; i < 4; i++) {
                uint32_t ra = (a_row + i * 16) * ROWB + kb + a_koff;
                ldm_x4(ah[i], aHi + ra);
                ldm_x4(al[i], aLo + ra);
            }
#pragma unroll
            for (int jp = 0; jp < 2; jp++) {
                uint32_t rb = (b_row4 + jp * 16) * ROWB + kb + b_koff4;
                uint32_t t4[4];
                ldm_x4(t4, bHi + rb);
                bh[jp * 2][0] = t4[0]; bh[jp * 2][1] = t4[1];
                bh[jp * 2 + 1][0] = t4[2]; bh[jp * 2 + 1][1] = t4[3];
                ldm_x4(t4, bLo + rb);
                bl[jp * 2][0] = t4[0]; bl[jp * 2][1] = t4[1];
                bl[jp * 2 + 1][0] = t4[2]; bl[jp * 2 + 1][1] = t4[3];
            }
#pragma unroll
            for (int i = 0; i < 4; i++)
#pragma unroll
                for (int j = 0; j < 4; j++) {
                    mma16816(acc[i][j], ah[i], bh[j]);
                    mma16816(acc[i][j], ah[i], bl[j]);
                    mma16816(acc[i][j], al[i], bh[j]);
                }
        }
        __syncthreads();
        if (ch + 2 < 16) {
            const int k0 = (ch + 2) * KCH;
            stage_issue(base, tid, Ahi + row0 * CC + k0, Alo + row0 * CC + k0,
                        Bhi + boff + k0, Blo + boff + k0);
        }
    }

    // ---- epilogue ----
    const int mrow = wm * 64 + (lane >> 2);
    const int mcol = wn * 32 + (lane & 3) * 2;

    if (MODE == 3) {
        // transposed bf16 hi/lo output via smem transpose
        uint16_t* shh = (uint16_t*)smem;              // [128 cols][130]
        uint16_t* shl = shh + 128 * 130;
#pragma unroll
        for (int i = 0; i < 4; i++)
#pragma unroll
            for (int half = 0; half < 2; half++) {
                int row = mrow + i * 16 + half * 8;   // local row
#pragma unroll
                for (int j = 0; j < 4; j++) {
                    int col = mcol + j * 8;           // local col
                    uint32_t h, l;
                    cvt2(acc[i][j][half * 2 + 0], acc[i][j][half * 2 + 1], h, l);
                    shh[col * 130 + row] = (uint16_t)h;
                    shh[(col + 1) * 130 + row] = (uint16_t)(h >> 16);
                    shl[col * 130 + row] = (uint16_t)l;
                    shl[(col + 1) * 130 + row] = (uint16_t)(l >> 16);
                }
            }
        __syncthreads();
        const int b = (int)(blockIdx.y >> 7);
        const size_t nl0 = (size_t)(blockIdx.y & 127) * 128;
        uint32_t* dh = (uint32_t*)Vhi;
        uint32_t* dl = (uint32_t*)Vlo;
#pragma unroll
        for (int it = 0; it < 32; it++) {
            int c = it * 4 + (tid >> 6);
            int w = tid & 63;
            uint32_t hv = *(uint32_t*)(&shh[c * 130 + 2 * w]);
            uint32_t lv = *(uint32_t*)(&shl[c * 130 + 2 * w]);
            size_t idx = ((((size_t)b * CC + n0 + c) * NTOK + nl0) >> 1) + w;
            dh[idx] = hv;
            dl[idx] = lv;
        }
        return;
    }

#pragma unroll
    for (int i = 0; i < 4; i++) {
#pragma unroll
        for (int half = 0; half < 2; half++) {
            size_t r = row0 + mrow + i * 16 + half * 8;
            size_t base = r * CC + n0 + mcol;
#pragma unroll
            for (int j = 0; j < 4; j++) {
                float2 v2;
                v2.x = acc[i][j][half * 2 + 0];
                v2.y = acc[i][j][half * 2 + 1];
                size_t off = base + j * 8;
                if (MODE == 1) {
                    float2 iv = *(const float2*)(illu + off);
                    *(float2*)(C2 + off) = v2;
                    uint32_t h, l;
                    cvt2(v2.x * iv.x, v2.y * iv.y, h, l);
                    ((uint32_t*)Vhi)[off >> 1] = h;
                    ((uint32_t*)Vlo)[off >> 1] = l;
                } else {
                    float2 bv = *(const float2*)(bias + n0 + mcol + j * 8);
                    v2.x += bv.x; v2.y += bv.y;
                    *(float2*)(C + off) = v2;
                }
            }
        }
    }
}

// ------------- norms from transposed bf16 hi/lo (contiguous rows) ----------
__global__ void normsq_t(const bf16* __restrict__ qh_, const bf16* __restrict__ ql_,
                         const bf16* __restrict__ kh_, const bf16* __restrict__ kl_,
                         float* __restrict__ iq, float* __restrict__ ik)
{
    const int c = blockIdx.x, b = blockIdx.y;
    const int tid = threadIdx.x;
    const size_t b32 = (((size_t)b * CC + c) * NTOK) >> 1;
    const uint32_t* qh = (const uint32_t*)qh_ + b32;
    const uint32_t* ql = (const uint32_t*)ql_ + b32;
    const uint32_t* kh = (const uint32_t*)kh_ + b32;
    const uint32_t* kl = (const uint32_t*)kl_ + b32;

    float sq = 0.f, sk = 0.f;
    for (int i = tid; i < NTOK / 2; i += 256) {
        uint32_t h = qh[i], l = ql[i];
        float f0 = bfu16_to_f(h & 0xFFFF) + bfu16_to_f(l & 0xFFFF);
        float f1 = bfu16_to_f(h >> 16) + bfu16_to_f(l >> 16);
        sq += f0 * f0 + f1 * f1;
        h = kh[i]; l = kl[i];
        f0 = bfu16_to_f(h & 0xFFFF) + bfu16_to_f(l & 0xFFFF);
        f1 = bfu16_to_f(h >> 16) + bfu16_to_f(l >> 16);
        sk += f0 * f0 + f1 * f1;
    }
    __shared__ float red[2][256];
    red[0][tid] = sq; red[1][tid] = sk;
    __syncthreads();
    for (int s = 128; s > 0; s >>= 1) {
        if (tid < s) {
            red[0][tid] += red[0][tid + s];
            red[1][tid] += red[1][tid + s];
        }
        __syncthreads();
    }
    if (tid == 0) {
        iq[b * CC + c] = 1.f / fmaxf(sqrtf(red[0][0]), 1e-12f);
        ik[b * CC + c] = 1.f / fmaxf(sqrtf(red[1][0]), 1e-12f);
    }
}

// ------------- Gram via mma with direct-LDG fragments ----------------------
__global__ void __launch_bounds__(256) gram_mma(
    const bf16* __restrict__ KThi, const bf16* __restrict__ KTlo,
    const bf16* __restrict__ QThi, const bf16* __restrict__ QTlo,
    float* __restrict__ part)
{
    const int h = blockIdx.x, b = blockIdx.y, s = blockIdx.z;
    const int wid = threadIdx.x >> 5, lane = threadIdx.x & 31;
    const int nbase = s * (NTOK / GSPLIT) + wid * 256;

    const size_t rowbase = ((size_t)b * CC + h * DHEAD) * NTOK;
    const bf16* Kh = KThi + rowbase;
    const bf16* Kl = KTlo + rowbase;
    const bf16* Qh = QThi + rowbase;
    const bf16* Ql = QTlo + rowbase;

    float acc[4][8][4];
#pragma unroll
    for (int i = 0; i < 4; i++)
#pragma unroll
        for (int j = 0; j < 8; j++)
#pragma unroll
            for (int t = 0; t < 4; t++) acc[i][j][t] = 0.f;

    const int rsel = lane >> 2;
    const int csel = (lane & 3) * 2;

    for (int step = 0; step < 16; step++) {
        const int nb = nbase + step * 16 + csel;
        uint32_t ah[4][4], al[4][4];
#pragma unroll
        for (int mt = 0; mt < 4; mt++) {
            const size_t r0 = (size_t)(mt * 16 + rsel) * NTOK;
            const size_t r8 = r0 + 8 * NTOK;
            ah[mt][0] = *(const uint32_t*)(Kh + r0 + nb);
            ah[mt][1] = *(const uint32_t*)(Kh + r8 + nb);
            ah[mt][2] = *(const uint32_t*)(Kh + r0 + nb + 8);
            ah[mt][3] = *(const uint32_t*)(Kh + r8 + nb + 8);
            al[mt][0] = *(const uint32_t*)(Kl + r0 + nb);
            al[mt][1] = *(const uint32_t*)(Kl + r8 + nb);
            al[mt][2] = *(const uint32_t*)(Kl + r0 + nb + 8);
            al[mt][3] = *(const uint32_t*)(Kl + r8 + nb + 8);
        }
#pragma unroll
        for (int nt = 0; nt < 8; nt++) {
            const size_t q0 = (size_t)(nt * 8 + rsel) * NTOK;
            uint32_t bh[2], bl[2];
            bh[0] = *(const uint32_t*)(Qh + q0 + nb);
            bh[1] = *(const uint32_t*)(Qh + q0 + nb + 8);
            bl[0] = *(const uint32_t*)(Ql + q0 + nb);
            bl[1] = *(const uint32_t*)(Ql + q0 + nb + 8);
#pragma unroll
            for (int mt = 0; mt < 4; mt++) {
                mma16816(acc[mt][nt], ah[mt], bh);
                mma16816(acc[mt][nt], ah[mt], bl);
                mma16816(acc[mt][nt], al[mt], bh);
            }
        }
    }

    const int sp = s * 8 + wid;
    float* dst = part + (((size_t)sp * BB + b) * NHEAD + h) * 4096;
#pragma unroll
    for (int mt = 0; mt < 4; mt++)
#pragma unroll
        for (int nt = 0; nt < 8; nt++) {
            int r = mt * 16 + rsel, c = nt * 8 + csel;
            dst[r * 64 + c]           = acc[mt][nt][0];
            dst[r * 64 + c + 1]       = acc[mt][nt][1];
            dst[(r + 8) * 64 + c]     = acc[mt][nt][2];
            dst[(r + 8) * 64 + c + 1] = acc[mt][nt][3];
        }
}

// ------------- softmax over e ----------------------------------------------
__global__ void softmax_kernel(const float* __restrict__ part,
                               const float* __restrict__ iq,
                               const float* __restrict__ ik,
                               const float* __restrict__ rescale,
                               float* __restrict__ attn)
{
    int bh = blockIdx.x;
    int b = bh / NHEAD, h = bh % NHEAD;
    int d = threadIdx.x;

    __shared__ float iq_s[64];
    iq_s[d] = iq[b * CC + h * DHEAD + d];
    float ik_d = ik[b * CC + h * DHEAD + d];
    float resc = rescale[h];
    __syncthreads();

    float row[64];
#pragma unroll
    for (int e = 0; e < 64; e++) row[e] = 0.f;
    for (int sp = 0; sp < GS_TOT; sp++) {
        const float* p = part + (((size_t)sp * BB + b) * NHEAD + h) * 4096 + d * 64;
#pragma unroll 8
        for (int e = 0; e < 64; e++) row[e] += p[e];
    }
    float m = -1e30f;
#pragma unroll
    for (int e = 0; e < 64; e++) {
        row[e] = row[e] * ik_d * iq_s[e] * resc;
        m = fmaxf(m, row[e]);
    }
    float sum = 0.f;
#pragma unroll
    for (int e = 0; e < 64; e++) {
        row[e] = __expf(row[e] - m);
        sum += row[e];
    }
    float inv = 1.f / sum;
    float* dst = attn + ((size_t)(b * NHEAD + h)) * 4096 + d * 64;
#pragma unroll
    for (int e = 0; e < 64; e++) dst[e] = row[e] * inv;
}

// ------------- Weff[b][h*64+e][j] = sum_d attn[b,h,d,e] * Wp[h*64+d][j] -----
__global__ void weff_kernel(const float* __restrict__ attn,
                            const float* __restrict__ Wp,
                            float* __restrict__ weff)
{
    int eg = blockIdx.x;
    int b = blockIdx.y;
    int tid = threadIdx.x;
    int h = eg >> 6, e = eg & 63;

    __shared__ float a_s[64];
    if (tid < 64) a_s[tid] = attn[((size_t)(b * NHEAD + h) * 64 + tid) * 64 + e];
    __syncthreads();

    for (int j = tid; j < CC; j += 256) {
        float acc = 0.f;
#pragma unroll
        for (int d = 0; d < 64; d++)
            acc += a_s[d] * Wp[(size_t)(h * 64 + d) * CC + j];
        weff[((size_t)b * CC + eg) * CC + j] = acc;
    }
}

// ------------- fused dwconv3 -> GELU -> dwconv3 (NHWC), SAME padding -------
// grid (W/16, H/16, BB*16), block 256 = 32 ch x 8 spatial
__global__ void __launch_bounds__(256) dwconv_fused(
    const float* __restrict__ in, const float* __restrict__ w1,
    const float* __restrict__ w2, float* __restrict__ out)
{
    __shared__ float t[18 * 18 * 32];
    const int chb = (blockIdx.z & 15) * 32;
    const int b = blockIdx.z >> 4;
    const int x0 = blockIdx.x * 16, y0 = blockIdx.y * 16;
    const int ch = threadIdx.x & 31;
    const int sp = threadIdx.x >> 5;

    float wv[9];
#pragma unroll
    for (int k = 0; k < 9; k++) wv[k] = w1[(chb + ch) * 9 + k];

    // conv1 + gelu on 18x18 halo tile
    for (int p = sp; p < 324; p += 8) {
        int ly = p / 18, lx = p - ly * 18;
        int gy = y0 + ly - 1, gx = x0 + lx - 1;
        float val = 0.f;
        if (gy >= 0 && gy < HH && gx >= 0 && gx < WW) {
            float acc = 0.f;
#pragma unroll
            for (int dy = -1; dy <= 1; dy++) {
                int yy = gy + dy;
                if (yy < 0 || yy > HH - 1) continue;
#pragma unroll
                for (int dx = -1; dx <= 1; dx++) {
                    int xx = gx + dx;
                    if (xx < 0 || xx > WW - 1) continue;
                    acc += in[(((size_t)b * HH + yy) * WW + xx) * CC + chb + ch] *
                           wv[(dy + 1) * 3 + (dx + 1)];
                }
            }
            val = 0.5f * acc * (1.f + erff(acc * 0.70710678118654752f));
        }
        t[p * 32 + ch] = val;
    }
    __syncthreads();

#pragma unroll
    for (int k = 0; k < 9; k++) wv[k] = w2[(chb + ch) * 9 + k];

    // conv2 on 16x16 interior, accumulate into out
    for (int p = sp; p < 256; p += 8) {
        int ly = p >> 4, lx = p & 15;
        float acc = 0.f;
#pragma unroll
        for (int dy = 0; dy < 3; dy++)
#pragma unroll
            for (int dx = 0; dx < 3; dx++)
                acc += t[((ly + dy) * 18 + lx + dx) * 32 + ch] * wv[dy * 3 + dx];
        size_t o = (((size_t)b * HH + y0 + ly) * WW + x0 + lx) * CC + chb + ch;
        out[o] += acc;
    }
}

// ---------------------------------------------------------------------------
extern "C" void kernel_launch(void* const* d_in, const int* in_sizes, int n_in,
                              void* d_out, int out_size)
{
    const float* x    = (const float*)d_in[0];
    const float* illu = (const float*)d_in[1];
    const float* Wq   = (const float*)d_in[2];
    const float* Wk   = (const float*)d_in[3];
    const float* Wv   = (const float*)d_in[4];
    const float* resc = (const float*)d_in[5];
    const float* Wp   = (const float*)d_in[6];
    const float* bp   = (const float*)d_in[7];
    const float* c1w  = (const float*)d_in[8];
    const float* c2w  = (const float*)d_in[9];
    float* out = (float*)d_out;

    float *vinp, *weff, *iq, *ik, *gp, *attn;
    bf16 *xhi, *xlo, *vhi, *vlo, *wThi, *wTlo, *wfhi, *wflo;
    bf16 *qthi, *qtlo, *kthi, *ktlo;
    cudaGetSymbolAddress((void**)&vinp, g_vinp);
    cudaGetSymbolAddress((void**)&weff, g_weff);
    cudaGetSymbolAddress((void**)&iq, g_invq);
    cudaGetSymbolAddress((void**)&ik, g_invk);
    cudaGetSymbolAddress((void**)&gp, g_gpart);
    cudaGetSymbolAddress((void**)&attn, g_attn);
    cudaGetSymbolAddress((void**)&xhi, g_xhi);
    cudaGetSymbolAddress((void**)&xlo, g_xlo);
    cudaGetSymbolAddress((void**)&vhi, g_vhi);
    cudaGetSymbolAddress((void**)&vlo, g_vlo);
    cudaGetSymbolAddress((void**)&wThi, g_wThi);
    cudaGetSymbolAddress((void**)&wTlo, g_wTlo);
    cudaGetSymbolAddress((void**)&wfhi, g_wfhi);
    cudaGetSymbolAddress((void**)&wflo, g_wflo);
    cudaGetSymbolAddress((void**)&qthi, g_qthi);
    cudaGetSymbolAddress((void**)&qtlo, g_qtlo);
    cudaGetSymbolAddress((void**)&kthi, g_kthi);
    cudaGetSymbolAddress((void**)&ktlo, g_ktlo);

    cudaFuncSetAttribute(gemm_bf<1>, cudaFuncAttributeMaxDynamicSharedMemorySize, GEMM_SMEM);
    cudaFuncSetAttribute(gemm_bf<2>, cudaFuncAttributeMaxDynamicSharedMemorySize, GEMM_SMEM);
    cudaFuncSetAttribute(gemm_bf<3>, cudaFuncAttributeMaxDynamicSharedMemorySize, GEMM_SMEM);

    // 0) conversions: x -> bf16 hi/lo; weights -> transposed bf16 hi/lo
    cvt_x<<<(int)((size_t)MTOT * CC / (256 * 8)), 256>>>(x, xhi, xlo);
    dim3 tb(32, 8);
    tcvt<<<dim3(8, 16, 1), tb>>>(Wq, wThi, wTlo, CC, 0, 0);
    tcvt<<<dim3(8, 16, 1), tb>>>(Wk, wThi + CC * CC, wTlo + CC * CC, CC, 0, 0);
    tcvt<<<dim3(8, 16, 1), tb>>>(Wv, wThi + 2 * CC * CC, wTlo + 2 * CC * CC, CC, 0, 0);

    // 1) projections: q,k straight to transposed bf16 hi/lo; v gated + raw
    dim3 gProj(CC / 128, MTOT / 128, 1);
    gemm_bf<3><<<gProj, 256, GEMM_SMEM>>>(xhi, xlo, wThi, wTlo,
        nullptr, nullptr, qthi, qtlo, nullptr, nullptr, 0, 0);
    gemm_bf<3><<<gProj, 256, GEMM_SMEM>>>(xhi, xlo, wThi + CC * CC, wTlo + CC * CC,
        nullptr, nullptr, kthi, ktlo, nullptr, nullptr, 0, 0);
    gemm_bf<1><<<gProj, 256, GEMM_SMEM>>>(xhi, xlo, wThi + 2 * CC * CC, wTlo + 2 * CC * CC,
        nullptr, vinp, vhi, vlo, illu, nullptr, 0, 0);

    // 2) norms from transposed layout (contiguous)
    normsq_t<<<dim3(CC, BB), 256>>>(qthi, qtlo, kthi, ktlo, iq, ik);

    // 3) gram on tensor pipe + softmax
    gram_mma<<<dim3(NHEAD, BB, GSPLIT), 256>>>(kthi, ktlo, qthi, qtlo, gp);
    softmax_kernel<<<BB * NHEAD, 64>>>(gp, iq, ik, resc, attn);

    // 4) fold attention into Wp; transpose-convert to bf16 [n][k]
    weff_kernel<<<dim3(CC, BB), 256>>>(attn, Wp, weff);
    tcvt<<<dim3(8, 16, BB), tb>>>(weff, wfhi, wflo, CC,
        (size_t)CC * CC, (size_t)CC * CC);

    // 5) out_c = V @ Weff_b + bp (batched)
    gemm_bf<2><<<dim3(CC / 128, NTOK / 128, BB), 256, GEMM_SMEM>>>(
        vhi, vlo, wfhi, wflo, out, nullptr, nullptr, nullptr, nullptr, bp,
        (size_t)NTOK, (size_t)CC * CC);

    // 6) positional branch: fused dwconv -> gelu -> dwconv, added to out
    dwconv_fused<<<dim3(WW / 16, HH / 16, BB * 16), 256>>>(vinp, c1w, c2w, out);
}